// round 9
// baseline (speedup 1.0000x reference)
#include <cuda_runtime.h>
#include <math.h>

#define NPTS 16384
#define NCELL 24
#define NCELL3 13824
#define INV_CELL 0.1875f            // NCELL / 128
#define CELLSZ 5.3333333f           // 128 / NCELL
#define SCAN_T 1024
#define CHUNK 14                    // ceil(13824 / 1024)
#define QBLK 256
#define QPG 4                       // lanes per query
#define NQBLK ((2 * NPTS) * QPG / QBLK)   // 512 query blocks

__device__ int g_cnt[2][NCELL3];
__device__ int g_start[2][NCELL3 + 1];
__device__ int g_cursor[2][NCELL3];
__device__ float4 g_pts[2][NPTS];   // cell-sorted; w = -0.5*||p||^2
__device__ float g_acc;
__device__ int g_done;

__device__ __forceinline__ int cell_of(float x, float y, float z) {
    int cx = min((int)(x * INV_CELL), NCELL - 1);
    int cy = min((int)(y * INV_CELL), NCELL - 1);
    int cz = min((int)(z * INV_CELL), NCELL - 1);
    return (cx * NCELL + cy) * NCELL + cz;
}

__global__ void count_kernel(const float* __restrict__ A,
                             const float* __restrict__ B) {
    int i = blockIdx.x * blockDim.x + threadIdx.x;   // 0 .. 2*NPTS-1
    int set = i >> 14;
    int idx = i & (NPTS - 1);
    const float* __restrict__ P = set ? B : A;
    float x = P[3 * idx], y = P[3 * idx + 1], z = P[3 * idx + 2];
    atomicAdd(&g_cnt[set][cell_of(x, y, z)], 1);
}

// 2 blocks (one per set): exclusive scan of 13824 counts; re-zero g_cnt after use.
__global__ void scan_kernel() {
    __shared__ int sh[SCAN_T];
    int set = blockIdx.x;
    int t = threadIdx.x;
    int base = t * CHUNK;

    int loc[CHUNK];
    int sum = 0;
    #pragma unroll
    for (int u = 0; u < CHUNK; u++) {
        int c = base + u;
        loc[u] = (c < NCELL3) ? g_cnt[set][c] : 0;
        sum += loc[u];
    }
    sh[t] = sum;
    __syncthreads();
    for (int off = 1; off < SCAN_T; off <<= 1) {
        int v = sh[t];
        int w = (t >= off) ? sh[t - off] : 0;
        __syncthreads();
        sh[t] = v + w;
        __syncthreads();
    }
    int excl = (t == 0) ? 0 : sh[t - 1];
    #pragma unroll
    for (int u = 0; u < CHUNK; u++) {
        int c = base + u;
        if (c < NCELL3) {
            g_start[set][c] = excl;
            g_cursor[set][c] = excl;
            g_cnt[set][c] = 0;          // ready for next graph replay
            excl += loc[u];
        }
    }
    if (t == SCAN_T - 1) g_start[set][NCELL3] = excl;   // = NPTS
}

__global__ void scatter_kernel(const float* __restrict__ A,
                               const float* __restrict__ B) {
    int i = blockIdx.x * blockDim.x + threadIdx.x;
    int set = i >> 14;
    int idx = i & (NPTS - 1);
    const float* __restrict__ P = set ? B : A;
    float x = P[3 * idx], y = P[3 * idx + 1], z = P[3 * idx + 2];
    int c = cell_of(x, y, z);
    int pos = atomicAdd(&g_cursor[set][c], 1);
    g_pts[set][pos] = make_float4(x, y, z, -0.5f * (x * x + y * y + z * z));
}

// 4 lanes cooperate per query. Groups are lane-aligned -> full-mask shfl safe.
__global__ __launch_bounds__(QBLK) void query_kernel(float* __restrict__ out) {
    __shared__ float red[QBLK / 32];
    int gtid = blockIdx.x * QBLK + threadIdx.x;
    int i = gtid >> 2;                 // query id: 0 .. 2*NPTS-1
    int lg = threadIdx.x & 3;          // lane in group
    int qs = i >> 14;
    int rs = qs ^ 1;
    int idx = i & (NPTS - 1);

    float4 q = g_pts[qs][idx];
    int qx = min((int)(q.x * INV_CELL), NCELL - 1);
    int qy = min((int)(q.y * INV_CELL), NCELL - 1);
    int qz = min((int)(q.z * INV_CELL), NCELL - 1);

    const int* __restrict__ start = g_start[rs];
    const float4* __restrict__ pts = g_pts[rs];

    int z0 = max(qz - 1, 0), z1 = min(qz + 1, NCELL - 1);
    float best = -1e30f;   // max over refs of e = q.r - 0.5*||r||^2

    // ---- radius-1: 9 (dx,dy) columns statically unrolled, split by lane%4 ----
    {
        int k = 0;
        #pragma unroll
        for (int dx = -1; dx <= 1; dx++) {
            #pragma unroll
            for (int dy = -1; dy <= 1; dy++) {
                if ((k & 3) == lg) {
                    int ix = qx + dx, iy = qy + dy;
                    if (ix >= 0 && ix < NCELL && iy >= 0 && iy < NCELL) {
                        int base = (ix * NCELL + iy) * NCELL;
                        int p0 = start[base + z0];
                        int p1 = start[base + z1 + 1];   // contiguous z-span
                        for (int p = p0; p < p1; p++) {
                            float4 t = pts[p];
                            float e = fmaf(q.x, t.x,
                                      fmaf(q.y, t.y, fmaf(q.z, t.z, t.w)));
                            best = fmaxf(best, e);
                        }
                    }
                }
                k++;
            }
        }
    }
    // group max (lanes of a group are xor-1/xor-2 adjacent)
    best = fmaxf(best, __shfl_xor_sync(0xFFFFFFFFu, best, 1));
    best = fmaxf(best, __shfl_xor_sync(0xFFFFFFFFu, best, 2));

    float d2 = -2.0f * (q.w + best);
    bool done = (d2 <= CELLSZ * CELLSZ);

    // ---- rare expansion: warp-collective; done groups still join the shfls ----
    for (int r = 2; r <= NCELL && !__all_sync(0xFFFFFFFFu, done); r++) {
        if (!done) {
            int x0 = max(qx - r, 0), x1 = min(qx + r, NCELL - 1);
            int y0 = max(qy - r, 0), y1 = min(qy + r, NCELL - 1);
            int zz0 = max(qz - r, 0), zz1 = min(qz + r, NCELL - 1);
            int k = 0;
            for (int ix = x0; ix <= x1; ix++)
                for (int iy = y0; iy <= y1; iy++) {
                    if ((k++ & 3) == lg) {
                        int base = (ix * NCELL + iy) * NCELL;
                        int p0 = start[base + zz0];
                        int p1 = start[base + zz1 + 1];
                        for (int p = p0; p < p1; p++) {
                            float4 t = pts[p];
                            float e = fmaf(q.x, t.x,
                                      fmaf(q.y, t.y, fmaf(q.z, t.z, t.w)));
                            best = fmaxf(best, e);
                        }
                    }
                }
        }
        best = fmaxf(best, __shfl_xor_sync(0xFFFFFFFFu, best, 1));
        best = fmaxf(best, __shfl_xor_sync(0xFFFFFFFFu, best, 2));
        if (!done) {
            d2 = -2.0f * (q.w + best);
            float rb = r * CELLSZ;
            done = (d2 <= rb * rb);
        }
    }

    d2 = -2.0f * (q.w + best);
    float v = (lg == 0) ? sqrtf(fmaxf(d2, 0.0f)) : 0.0f;

    // ---- block sum -> global atomic; last block writes out + resets state ----
    #pragma unroll
    for (int o = 16; o > 0; o >>= 1) v += __shfl_down_sync(0xFFFFFFFFu, v, o);
    int lane = threadIdx.x & 31, wid = threadIdx.x >> 5;
    if (lane == 0) red[wid] = v;
    __syncthreads();
    if (threadIdx.x == 0) {
        float bs = 0.0f;
        #pragma unroll
        for (int w = 0; w < QBLK / 32; w++) bs += red[w];
        atomicAdd(&g_acc, bs);
        __threadfence();
        int t = atomicAdd(&g_done, 1);
        if (t == NQBLK - 1) {
            float total = *((volatile float*)&g_acc);
            out[0] = total * (1.0f / (2.0f * NPTS));
            g_acc = 0.0f;                 // reset for next graph replay
            g_done = 0;
        }
    }
}

extern "C" void kernel_launch(void* const* d_in, const int* in_sizes, int n_in,
                              void* d_out, int out_size) {
    const float* a = (const float*)d_in[0];
    const float* b = (const float*)d_in[1];
    float* out = (float*)d_out;

    count_kernel<<<(2 * NPTS) / 256, 256>>>(a, b);
    scan_kernel<<<2, SCAN_T>>>();
    scatter_kernel<<<(2 * NPTS) / 256, 256>>>(a, b);
    query_kernel<<<NQBLK, QBLK>>>(out);
}